// round 2
// baseline (speedup 1.0000x reference)
#include <cuda_runtime.h>

#define B_TOTAL 32768
#define T_LEN   200

// Scratch (allocation-free rule: __device__ globals)
__device__ float g_xT[2 * T_LEN * B_TOTAL];   // [channel][t][b]  (52.4 MB)
__device__ float g_weff[408];                 // w_eff[400] + combined bias at [400]

struct Params {
    const float* p[29];
    float* out;
};

typedef unsigned long long ull;

// ---- f32x2 helpers (sm_103a packed fp32; ptxas never auto-fuses these) ----
__device__ __forceinline__ ull pk(float lo, float hi) {
    ull r; asm("mov.b64 %0, {%1, %2};" : "=l"(r) : "f"(lo), "f"(hi)); return r;
}
__device__ __forceinline__ void upk(ull v, float& lo, float& hi) {
    asm("mov.b64 {%0, %1}, %2;" : "=f"(lo), "=f"(hi) : "l"(v));
}
__device__ __forceinline__ void ffma2(ull& d, ull a, ull b) {
    asm("fma.rn.f32x2 %0, %1, %2, %0;" : "+l"(d) : "l"(a), "l"(b));
}

// ---- fast activations (hot loop): MUFU.TANH based ----
__device__ __forceinline__ float tanha(float x) {
    float r; asm("tanh.approx.f32 %0, %1;" : "=f"(r) : "f"(x)); return r;
}
__device__ __forceinline__ float siga(float x) {
    return fmaf(tanha(0.5f * x), 0.5f, 0.5f);
}
// ---- accurate activations (epilogue/tail, executed O(1) per element) ----
__device__ __forceinline__ float sigacc(float x) {
    return __fdividef(1.0f, 1.0f + __expf(-x));
}
__device__ __forceinline__ float tanhacc(float x) {
    float e = __expf(-2.0f * x);
    return __fdividef(2.0f, 1.0f + e) - 1.0f;
}

// ---------------------------------------------------------------------------
// Fold Wp/bp/b3/W3[40:] into a single 400-vector + scalar:
//   out = sigmoid( W3[:40]@z2 + sum_p w_eff[p]*x_flat[p] + beff )
// ---------------------------------------------------------------------------
__global__ void k_prep(const float* __restrict__ Wp, const float* __restrict__ bp,
                       const float* __restrict__ W3, const float* __restrict__ b3) {
    int p = blockIdx.x * blockDim.x + threadIdx.x;
    if (p < 400) {
        float s = 0.f;
        for (int v = 0; v < 40; ++v) s = fmaf(W3[40 + v], Wp[v * 400 + p], s);
        g_weff[p] = s;
    } else if (p == 400) {
        float s = b3[0];
        for (int v = 0; v < 40; ++v) s = fmaf(W3[40 + v], bp[v], s);
        g_weff[400] = s;
    }
}

// ---------------------------------------------------------------------------
// x[B][2][200] -> g_xT[2*200][B]  (32x32 shared-tile transpose)
// ---------------------------------------------------------------------------
__global__ void k_transpose(const float* __restrict__ x) {
    __shared__ float tile[32][33];
    int p0 = blockIdx.x * 32, b0 = blockIdx.y * 32;
    int tx = threadIdx.x, ty = threadIdx.y;
    #pragma unroll
    for (int i = ty; i < 32; i += 8) {
        int p = p0 + tx, bb = b0 + i;
        tile[i][tx] = (p < 400) ? x[(size_t)bb * 400 + p] : 0.f;
    }
    __syncthreads();
    #pragma unroll
    for (int i = ty; i < 32; i += 8) {
        int p = p0 + i, bb = b0 + tx;
        if (p < 400) g_xT[(size_t)p * B_TOTAL + bb] = tile[tx][i];
    }
}

// ---------------------------------------------------------------------------
// Main fused kernel. Thread b runs both 2-layer LSTMs (f32x2-packed gates),
// streams the WH/WL projection into 64 packed f32x2 accumulators, folds the
// W1 half-GEMM per recurrence, then the W2/W3 tail — all weights via smem.
//
// smem: sW [8 tiles][4 u][132 floats]  (4224 f, also reused for W1/W2 stages)
//       zp [80][128]                   (10240 f)
//       sml small packed weights + bF + weff (576 f)
// ---------------------------------------------------------------------------
#define SW_STRIDE_U 132
#define SW_STRIDE_T 528
#define SW_FLOATS   4224
#define ZP_FLOATS   10240
#define SML_FLOATS  576

__global__ void __launch_bounds__(128, 2) k_main(Params P) {
    extern __shared__ float smem[];
    float* sWf = smem;                         // 4224 floats
    float* zp  = smem + SW_FLOATS;             // 10240 floats
    float* sml = smem + SW_FLOATS + ZP_FLOATS; // 576 floats

    const int tid = threadIdx.x;
    const int b   = blockIdx.x * 128 + tid;

    // init z_pre columns with b1 (per-thread column: no race)
    {
        const float* b1 = P.p[24];
        #pragma unroll
        for (int u = 0; u < 80; ++u) zp[u * 128 + tid] = b1[u];
    }

    float so = g_weff[400];   // folded-'other' running dot (incl. b3 + W3b@bp)
    ull acc2[64];             // 64 packed pairs = acc[128]

    #pragma unroll 1
    for (int r = 0; r < 2; ++r) {
        const float*  Wih0 = P.p[1 + 8 * r];
        const float*  Whh0 = P.p[2 + 8 * r];
        const float*  bih0 = P.p[3 + 8 * r];
        const float*  bhh0 = P.p[4 + 8 * r];
        const float*  Wih1 = P.p[5 + 8 * r];
        const float*  Whh1 = P.p[6 + 8 * r];
        const float*  bih1 = P.p[7 + 8 * r];
        const float*  bhh1 = P.p[8 + 8 * r];
        const float4* WHg  = (const float4*)P.p[19 + 2 * r];  // [128 rows][200 float4]
        const float*  bF   = P.p[20 + 2 * r];
        const float*  xTc  = g_xT + r * (T_LEN * B_TOTAL);

        __syncthreads();   // previous phase done with sml/sWf
        // ---- stage small weights, packed for f32x2 consumption ----
        // sml[0:16)  Wih0            (natural pair order)
        // sml[16:32) bih0+bhh0       sml[32:48) bih1+bhh1
        // sml[48:112)  Whh0 packed [j][16]: pos j*16+k holds Whh0[k][j]
        // sml[112:176) Wih1 packed   sml[176:240) Whh1 packed
        // sml[240:368) bF            sml[368:568) weff
        if (tid < 16) {
            sml[tid]      = Wih0[tid];
            sml[16 + tid] = bih0[tid] + bhh0[tid];
            sml[32 + tid] = bih1[tid] + bhh1[tid];
        }
        if (tid < 64) {
            int j = tid >> 4, k = tid & 15;
            sml[48  + tid] = Whh0[k * 4 + j];
            sml[112 + tid] = Wih1[k * 4 + j];
            sml[176 + tid] = Whh1[k * 4 + j];
        }
        sml[240 + tid] = bF[tid];
        for (int i = tid; i < 200; i += 128) sml[368 + i] = g_weff[r * T_LEN + i];
        __syncthreads();

        float h0[4]  = {0.f, 0.f, 0.f, 0.f};
        float c0v[4] = {0.f, 0.f, 0.f, 0.f};
        float h1[4]  = {0.f, 0.f, 0.f, 0.f};
        float c1v[4] = {0.f, 0.f, 0.f, 0.f};
        ull h0p[4] = {0ULL, 0ULL, 0ULL, 0ULL};
        ull h1p[4] = {0ULL, 0ULL, 0ULL, 0ULL};
        #pragma unroll
        for (int jp = 0; jp < 64; ++jp) acc2[jp] = 0ULL;

        #pragma unroll 1
        for (int tile = 0; tile < 25; ++tile) {
            __syncthreads();
            // stage WH[:, 32*tile .. +31] -> sW[tt][u][j] (padded stride 132)
            // global reads fully coalesced (8 consecutive float4 per 8 lanes)
            #pragma unroll
            for (int q = 0; q < 8; ++q) {
                int idx = tid + q * 128;
                int j = idx >> 3, tt = idx & 7;
                float4 w = WHg[j * 200 + tile * 8 + tt];
                float* dst = sWf + tt * SW_STRIDE_T + j;
                dst[0 * SW_STRIDE_U] = w.x;
                dst[1 * SW_STRIDE_U] = w.y;
                dst[2 * SW_STRIDE_U] = w.z;
                dst[3 * SW_STRIDE_U] = w.w;
            }
            __syncthreads();

            #pragma unroll 1
            for (int tt = 0; tt < 8; ++tt) {
                const int t = tile * 8 + tt;
                const float xv = xTc[t * B_TOTAL + b];
                so = fmaf(sml[368 + t], xv, so);
                const ull xvp = pk(xv, xv);

                ull gp[8];
                // ---- layer 0: g = x*Wih0 + b0 + Whh0 @ h0 (packed pairs) ----
                {
                    const ulonglong2* wx = (const ulonglong2*)(sml);
                    const ulonglong2* bb = (const ulonglong2*)(sml + 16);
                    #pragma unroll
                    for (int k2 = 0; k2 < 4; ++k2) {
                        ulonglong2 w = wx[k2], bv = bb[k2];
                        gp[2 * k2]     = bv.x; ffma2(gp[2 * k2],     w.x, xvp);
                        gp[2 * k2 + 1] = bv.y; ffma2(gp[2 * k2 + 1], w.y, xvp);
                    }
                    #pragma unroll
                    for (int j = 0; j < 4; ++j) {
                        const ulonglong2* wr = (const ulonglong2*)(sml + 48 + j * 16);
                        #pragma unroll
                        for (int k2 = 0; k2 < 4; ++k2) {
                            ulonglong2 w = wr[k2];
                            ffma2(gp[2 * k2],     w.x, h0p[j]);
                            ffma2(gp[2 * k2 + 1], w.y, h0p[j]);
                        }
                    }
                }
                {
                    float g[16];
                    #pragma unroll
                    for (int k2 = 0; k2 < 8; ++k2) upk(gp[k2], g[2 * k2], g[2 * k2 + 1]);
                    #pragma unroll
                    for (int u = 0; u < 4; ++u) {
                        float ig = siga(g[u]);
                        float fg = siga(g[u + 4]);
                        float gg = tanha(g[u + 8]);
                        float og = siga(g[u + 12]);
                        c0v[u] = fmaf(fg, c0v[u], ig * gg);
                        h0[u]  = og * tanha(c0v[u]);
                        h0p[u] = pk(h0[u], h0[u]);
                    }
                }
                // ---- layer 1: g = b1s + Wih1 @ h0_new + Whh1 @ h1 ----
                {
                    const ulonglong2* bb = (const ulonglong2*)(sml + 32);
                    #pragma unroll
                    for (int k2 = 0; k2 < 4; ++k2) {
                        ulonglong2 bv = bb[k2];
                        gp[2 * k2] = bv.x; gp[2 * k2 + 1] = bv.y;
                    }
                    #pragma unroll
                    for (int j = 0; j < 4; ++j) {
                        const ulonglong2* wa = (const ulonglong2*)(sml + 112 + j * 16);
                        const ulonglong2* wb = (const ulonglong2*)(sml + 176 + j * 16);
                        #pragma unroll
                        for (int k2 = 0; k2 < 4; ++k2) {
                            ulonglong2 a = wa[k2], w = wb[k2];
                            ffma2(gp[2 * k2],     a.x, h0p[j]);
                            ffma2(gp[2 * k2 + 1], a.y, h0p[j]);
                            ffma2(gp[2 * k2],     w.x, h1p[j]);
                            ffma2(gp[2 * k2 + 1], w.y, h1p[j]);
                        }
                    }
                }
                {
                    float g[16];
                    #pragma unroll
                    for (int k2 = 0; k2 < 8; ++k2) upk(gp[k2], g[2 * k2], g[2 * k2 + 1]);
                    #pragma unroll
                    for (int u = 0; u < 4; ++u) {
                        float ig = siga(g[u]);
                        float fg = siga(g[u + 4]);
                        float gg = tanha(g[u + 8]);
                        float og = siga(g[u + 12]);
                        c1v[u] = fmaf(fg, c1v[u], ig * gg);
                        h1[u]  = og * tanha(c1v[u]);
                        h1p[u] = pk(h1[u], h1[u]);
                    }
                }
                // ---- streamed projection: acc += WH[:, 4t:4t+4] @ h1 ----
                {
                    const float* wt = sWf + tt * SW_STRIDE_T;
                    #pragma unroll
                    for (int u = 0; u < 4; ++u) {
                        const ulonglong2* wrow = (const ulonglong2*)(wt + u * SW_STRIDE_U);
                        #pragma unroll
                        for (int q = 0; q < 32; ++q) {
                            ulonglong2 w = wrow[q];   // LDS.128, broadcast
                            ffma2(acc2[2 * q],     w.x, h1p[u]);
                            ffma2(acc2[2 * q + 1], w.y, h1p[u]);
                        }
                    }
                }
            }
        }

        // ---- epilogue: Hf/Lf = tanh(acc + bF), fold via W1 half-columns ----
        #pragma unroll
        for (int jp = 0; jp < 64; ++jp) {
            float a, bv; upk(acc2[jp], a, bv);
            a  = tanhacc(a  + sml[240 + 2 * jp]);
            bv = tanhacc(bv + sml[240 + 2 * jp + 1]);
            acc2[jp] = pk(a, bv);
        }
        const float* W1 = P.p[23];
        #pragma unroll 1
        for (int u0 = 0; u0 < 80; u0 += 32) {
            const int nu = (u0 == 64) ? 16 : 32;
            __syncthreads();
            for (int i = tid; i < nu * 32; i += 128) {
                int uu = i >> 5, q = i & 31;
                ((float4*)sWf)[uu * 32 + q] =
                    *(const float4*)(W1 + (u0 + uu) * 256 + r * 128 + q * 4);
            }
            __syncthreads();
            #pragma unroll 1
            for (int u = 0; u < nu; ++u) {
                const ulonglong2* w1 = (const ulonglong2*)(sWf + u * 128);
                ull s0 = 0ULL, s1 = 0ULL, s2 = 0ULL, s3 = 0ULL;
                #pragma unroll
                for (int q = 0; q < 32; q += 2) {
                    ulonglong2 wa = w1[q], wb = w1[q + 1];
                    ffma2(s0, wa.x, acc2[2 * q]);
                    ffma2(s1, wa.y, acc2[2 * q + 1]);
                    ffma2(s2, wb.x, acc2[2 * q + 2]);
                    ffma2(s3, wb.y, acc2[2 * q + 3]);
                }
                float a0, a1, a2, a3, a4, a5, a6, a7;
                upk(s0, a0, a1); upk(s1, a2, a3); upk(s2, a4, a5); upk(s3, a6, a7);
                zp[(u0 + u) * 128 + tid] += (a0 + a1) + (a2 + a3) + (a4 + a5) + (a6 + a7);
            }
        }
    }

    // ---- tail: z1 = tanh(zp); z2 = tanh(W2@z1+b2); out = sig(W3a@z2 + so) ----
    __syncthreads();
    {
        const float* W2 = P.p[25];
        const float* b2 = P.p[26];
        const float* W3 = P.p[27];
        for (int i = tid; i < 800; i += 128)
            ((float4*)sWf)[i] = ((const float4*)W2)[i];
        if (tid < 40) { sWf[3200 + tid] = b2[tid]; sWf[3240 + tid] = W3[tid]; }
    }
    __syncthreads();

    ull z1p[40];
    #pragma unroll
    for (int q = 0; q < 40; ++q) {
        float a = tanhacc(zp[(2 * q) * 128 + tid]);
        float c = tanhacc(zp[(2 * q + 1) * 128 + tid]);
        z1p[q] = pk(a, c);
    }
    float r3 = so;
    #pragma unroll 1
    for (int u2 = 0; u2 < 40; ++u2) {
        const ulonglong2* w2 = (const ulonglong2*)(sWf + u2 * 80);
        ull s0 = 0ULL, s1 = 0ULL, s2 = 0ULL, s3 = 0ULL;
        #pragma unroll
        for (int q = 0; q < 20; q += 2) {
            ulonglong2 wa = w2[q], wb = w2[q + 1];
            ffma2(s0, wa.x, z1p[2 * q]);
            ffma2(s1, wa.y, z1p[2 * q + 1]);
            ffma2(s2, wb.x, z1p[2 * q + 2]);
            ffma2(s3, wb.y, z1p[2 * q + 3]);
        }
        float a0, a1, a2, a3, a4, a5, a6, a7;
        upk(s0, a0, a1); upk(s1, a2, a3); upk(s2, a4, a5); upk(s3, a6, a7);
        float s = sWf[3200 + u2] + (a0 + a1) + (a2 + a3) + (a4 + a5) + (a6 + a7);
        r3 = fmaf(sWf[3240 + u2], tanhacc(s), r3);
    }
    P.out[b] = sigacc(r3);
}

extern "C" void kernel_launch(void* const* d_in, const int* in_sizes, int n_in,
                              void* d_out, int out_size) {
    (void)in_sizes; (void)n_in; (void)out_size;
    Params P;
    for (int i = 0; i < 29; ++i) P.p[i] = (const float*)d_in[i];
    P.out = (float*)d_out;

    const size_t shmem = (size_t)(SW_FLOATS + ZP_FLOATS + SML_FLOATS) * sizeof(float);
    cudaFuncSetAttribute(k_main, cudaFuncAttributeMaxDynamicSharedMemorySize, (int)shmem);

    k_prep<<<1, 512>>>(P.p[17], P.p[18], P.p[27], P.p[28]);

    dim3 tb(32, 8);
    dim3 tg(13, B_TOTAL / 32);
    k_transpose<<<tg, tb>>>(P.p[0]);

    k_main<<<256, 128, shmem>>>(P);
}

// round 10
// speedup vs baseline: 1.4502x; 1.4502x over previous
#include <cuda_runtime.h>

#define B_TOTAL 32768
#define T_LEN   200

// Scratch (allocation-free rule: __device__ globals)
__device__ float g_Hh[2 * 800 * B_TOTAL];   // [r][k=4t+u][b]   210 MB
__device__ float g_so[2 * B_TOTAL];         // folded-'other' partial dots
__device__ float g_WT[2 * 800 * 128];       // WH/WL transposed: [r][k][n]

struct Params {
    const float* p[29];
    float* out;
};

typedef unsigned long long ull;

// ---- f32x2 helpers (sm_103a packed fp32) ----
__device__ __forceinline__ ull pk(float lo, float hi) {
    ull r; asm("mov.b64 %0, {%1, %2};" : "=l"(r) : "f"(lo), "f"(hi)); return r;
}
__device__ __forceinline__ void upk(ull v, float& lo, float& hi) {
    asm("mov.b64 {%0, %1}, %2;" : "=f"(lo), "=f"(hi) : "l"(v));
}
__device__ __forceinline__ void ffma2(ull& d, ull a, ull b) {
    asm("fma.rn.f32x2 %0, %1, %2, %0;" : "+l"(d) : "l"(a), "l"(b));
}

// ---- fast activations (hot loop): MUFU.TANH — validated at rel_err 2.3e-7 in R2 ----
__device__ __forceinline__ float tanha(float x) {
    float r; asm("tanh.approx.f32 %0, %1;" : "=f"(r) : "f"(x)); return r;
}
__device__ __forceinline__ float siga(float x) {
    return fmaf(tanha(0.5f * x), 0.5f, 0.5f);
}
// ---- accurate activations (epilogue/tail only) ----
__device__ __forceinline__ float sigacc(float x) {
    return __fdividef(1.0f, 1.0f + __expf(-x));
}
__device__ __forceinline__ float tanhacc(float x) {
    float e = __expf(-2.0f * x);
    return __fdividef(2.0f, 1.0f + e) - 1.0f;
}

// ---------------------------------------------------------------------------
// Transpose WH/WL -> g_WT[r][k][n]  (820 KB once; makes GEMM staging trivial)
// ---------------------------------------------------------------------------
__global__ void k_wt(const float* __restrict__ WH, const float* __restrict__ WL) {
    int r = blockIdx.y;
    const float* __restrict__ W = r ? WL : WH;
    int idx = blockIdx.x * 1024 + threadIdx.x;
    if (idx < 102400) {
        int k = idx >> 7, n = idx & 127;
        g_WT[r * 102400 + idx] = W[n * 800 + k];
    }
}

// ---------------------------------------------------------------------------
// k_lstm: block (bx, r). Thread = element b, runs ONE 2-layer LSTM recurrence.
// Writes h1(t) transposed to g_Hh[r][4t+u][b] (coalesced STG.32 x4 per step)
// and the folded-'other' partial dot to g_so[r][b].
// MUFU-bound (~40 MUFU.TANH/step/thread); occ 4 hides everything else.
// ---------------------------------------------------------------------------
__global__ void __launch_bounds__(128, 4) k_lstm(Params P) {
    __shared__ float sml[256];
    __shared__ float wef[200];

    const int tid = threadIdx.x;
    const int r   = blockIdx.y;
    const int b   = blockIdx.x * 128 + tid;

    const float* __restrict__ Wih0 = P.p[1 + 8 * r];
    const float* __restrict__ Whh0 = P.p[2 + 8 * r];
    const float* __restrict__ bih0 = P.p[3 + 8 * r];
    const float* __restrict__ bhh0 = P.p[4 + 8 * r];
    const float* __restrict__ Wih1 = P.p[5 + 8 * r];
    const float* __restrict__ Whh1 = P.p[6 + 8 * r];
    const float* __restrict__ bih1 = P.p[7 + 8 * r];
    const float* __restrict__ bhh1 = P.p[8 + 8 * r];

    // ---- stage small weights packed for f32x2 ----
    // sml[0:16) Wih0   [16:32) bih0+bhh0   [32:48) bih1+bhh1
    // [48:112) Whh0 packed [j][16] (pos j*16+k = W[k][j])
    // [112:176) Wih1 packed   [176:240) Whh1 packed
    if (tid < 16) {
        sml[tid]      = Wih0[tid];
        sml[16 + tid] = bih0[tid] + bhh0[tid];
        sml[32 + tid] = bih1[tid] + bhh1[tid];
    }
    if (tid < 64) {
        int j = tid >> 4, k = tid & 15;
        sml[48  + tid] = Whh0[k * 4 + j];
        sml[112 + tid] = Wih1[k * 4 + j];
        sml[176 + tid] = Whh1[k * 4 + j];
    }
    // weff_r[t] = sum_v W3[40+v] * Wp[v][r*200 + t]
    {
        const float* __restrict__ Wp  = P.p[17];
        const float* __restrict__ W3b = P.p[27] + 40;
        for (int t = tid; t < 200; t += 128) {
            float s = 0.f;
            #pragma unroll 8
            for (int v = 0; v < 40; ++v) s = fmaf(W3b[v], Wp[v * 400 + r * 200 + t], s);
            wef[t] = s;
        }
    }
    __syncthreads();

    const float* __restrict__ xrow = P.p[0] + (size_t)b * 400 + r * 200;
    float* __restrict__ hB = g_Hh + (size_t)r * 800 * B_TOTAL + b;

    float c0v[4] = {0.f, 0.f, 0.f, 0.f};
    float c1v[4] = {0.f, 0.f, 0.f, 0.f};
    ull h0p[4] = {0ULL, 0ULL, 0ULL, 0ULL};
    ull h1p[4] = {0ULL, 0ULL, 0ULL, 0ULL};
    float so = 0.f;
    size_t hoff = 0;

    #pragma unroll 1
    for (int t4 = 0; t4 < 50; ++t4) {
        float4 xq = *(const float4*)(xrow + t4 * 4);
        float xs[4] = {xq.x, xq.y, xq.z, xq.w};
        #pragma unroll
        for (int s = 0; s < 4; ++s) {
            const int t = t4 * 4 + s;
            const float xv = xs[s];
            so = fmaf(wef[t], xv, so);
            const ull xvp = pk(xv, xv);

            ull gp[8];
            // layer 0: g = x*Wih0 + b0 + Whh0 @ h0
            {
                const ulonglong2* wx = (const ulonglong2*)(sml);
                const ulonglong2* bb = (const ulonglong2*)(sml + 16);
                #pragma unroll
                for (int k2 = 0; k2 < 4; ++k2) {
                    ulonglong2 w = wx[k2], bv = bb[k2];
                    gp[2 * k2]     = bv.x; ffma2(gp[2 * k2],     w.x, xvp);
                    gp[2 * k2 + 1] = bv.y; ffma2(gp[2 * k2 + 1], w.y, xvp);
                }
                #pragma unroll
                for (int j = 0; j < 4; ++j) {
                    const ulonglong2* wr = (const ulonglong2*)(sml + 48 + j * 16);
                    #pragma unroll
                    for (int k2 = 0; k2 < 4; ++k2) {
                        ulonglong2 w = wr[k2];
                        ffma2(gp[2 * k2],     w.x, h0p[j]);
                        ffma2(gp[2 * k2 + 1], w.y, h0p[j]);
                    }
                }
            }
            {
                float g[16];
                #pragma unroll
                for (int k2 = 0; k2 < 8; ++k2) upk(gp[k2], g[2 * k2], g[2 * k2 + 1]);
                #pragma unroll
                for (int u = 0; u < 4; ++u) {
                    float ig = siga(g[u]);
                    float fg = siga(g[u + 4]);
                    float gg = tanha(g[u + 8]);
                    float og = siga(g[u + 12]);
                    c0v[u] = fmaf(fg, c0v[u], ig * gg);
                    float h = og * tanha(c0v[u]);
                    h0p[u] = pk(h, h);
                }
            }
            // layer 1: g = b1s + Wih1 @ h0_new + Whh1 @ h1
            {
                const ulonglong2* bb = (const ulonglong2*)(sml + 32);
                #pragma unroll
                for (int k2 = 0; k2 < 4; ++k2) {
                    ulonglong2 bv = bb[k2];
                    gp[2 * k2] = bv.x; gp[2 * k2 + 1] = bv.y;
                }
                #pragma unroll
                for (int j = 0; j < 4; ++j) {
                    const ulonglong2* wa = (const ulonglong2*)(sml + 112 + j * 16);
                    const ulonglong2* wb = (const ulonglong2*)(sml + 176 + j * 16);
                    #pragma unroll
                    for (int k2 = 0; k2 < 4; ++k2) {
                        ulonglong2 a = wa[k2], w = wb[k2];
                        ffma2(gp[2 * k2],     a.x, h0p[j]);
                        ffma2(gp[2 * k2 + 1], a.y, h0p[j]);
                        ffma2(gp[2 * k2],     w.x, h1p[j]);
                        ffma2(gp[2 * k2 + 1], w.y, h1p[j]);
                    }
                }
            }
            {
                float g[16];
                #pragma unroll
                for (int k2 = 0; k2 < 8; ++k2) upk(gp[k2], g[2 * k2], g[2 * k2 + 1]);
                #pragma unroll
                for (int u = 0; u < 4; ++u) {
                    float ig = siga(g[u]);
                    float fg = siga(g[u + 4]);
                    float gg = tanha(g[u + 8]);
                    float og = siga(g[u + 12]);
                    c1v[u] = fmaf(fg, c1v[u], ig * gg);
                    float h = og * tanha(c1v[u]);
                    h1p[u] = pk(h, h);
                    hB[hoff + (size_t)u * B_TOTAL] = h;   // coalesced across warp
                }
            }
            hoff += 4 * B_TOTAL;
        }
    }
    g_so[r * B_TOTAL + b] = so;
}

// ---------------------------------------------------------------------------
// k_gemm: per block, 64 batch rows. C[64][256] = tanh(Hh @ W^T + b) for both
// halves (register-tiled f32x2 GEMM), then fused W1/W2/W3 tail + sigmoid.
// 256 threads; thread tile 4 rows x 8 cols (16 f32x2 accs per half).
// ---------------------------------------------------------------------------
#define ZC_STRIDE 268
#define ZC_FL     (64 * ZC_STRIDE)          // 17152
#define R1_FL     12800                     // sA(64x68=4352) + sB(64x132=8448)
#define SA_OFF    0
#define SB_OFF    4352
#define Z1_STRIDE 84
#define Z1_FL     (64 * Z1_STRIDE)          // 5376
#define Z2_STRIDE 44
#define Z2_FL     (64 * Z2_STRIDE)          // 2816
#define SW1_STRIDE 260
#define SW2_STRIDE 84
#define GEMM_SMEM_FL (ZC_FL + R1_FL + Z1_FL + Z2_FL + 416)

__global__ void __launch_bounds__(256, 1) k_gemm(Params P) {
    extern __shared__ float smem[];
    float* zc  = smem;                       // [64][268]
    float* r1  = smem + ZC_FL;               // sA/sB | sW1 | sW2
    float* z1s = r1 + R1_FL;                 // [64][84]
    float* z2s = z1s + Z1_FL;                // [64][44]
    float* sbias = z2s + Z2_FL;              // [256] bH|bL
    float* sb1 = sbias + 256;                // [80]
    float* sb2 = sb1 + 80;                   // [40]
    float* sw3 = sb2 + 40;                   // [40]

    const int tid = threadIdx.x;
    const int m0  = blockIdx.x * 64;
    const int rg  = tid & 15;                // row group: rows rg*4..+4
    const int cg  = tid >> 4;                // col group: cols cg*8..+8

    // stage biases/tail vectors
    if (tid < 128) {
        sbias[tid]       = P.p[20][tid];     // bH
        sbias[128 + tid] = P.p[22][tid];     // bL
    }
    if (tid < 80) sb1[tid] = P.p[24][tid];
    if (tid < 40) { sb2[tid] = P.p[26][tid]; sw3[tid] = P.p[27][tid]; }

    float* sA = r1 + SA_OFF;                 // [kc][68]: sA[k*68+row]
    float* sB = r1 + SB_OFF;                 // [kc][132]: sB[k*132+n]

    #pragma unroll 1
    for (int half = 0; half < 2; ++half) {
        const float* __restrict__ Hh = g_Hh + (size_t)half * 800 * B_TOTAL;  // [800][B]
        const float* __restrict__ WT = g_WT + half * 102400;                 // [800][128]

        ull acc[4][4];
        #pragma unroll
        for (int i = 0; i < 4; ++i)
            #pragma unroll
            for (int p = 0; p < 4; ++p) acc[i][p] = 0ULL;

        #pragma unroll 1
        for (int k0 = 0; k0 < 800; k0 += 64) {
            const int kc = (k0 == 768) ? 32 : 64;
            __syncthreads();
            // stage A: sA[k][row] = Hh[k0+k][m0+row]  (coalesced, direct layout)
            for (int idx = tid; idx < kc * 16; idx += 256) {
                int rq = idx & 15, k = idx >> 4;
                float4 v = *(const float4*)(Hh + (size_t)(k0 + k) * B_TOTAL + m0 + rq * 4);
                *(float4*)(sA + k * 68 + rq * 4) = v;
            }
            // stage B: sB[k][n] = WT[k0+k][n]  (coalesced, conflict-free)
            for (int idx = tid; idx < kc * 32; idx += 256) {
                int nq = idx & 31, k = idx >> 5;
                float4 v = *(const float4*)(WT + (k0 + k) * 128 + nq * 4);
                *(float4*)(sB + k * 132 + nq * 4) = v;
            }
            __syncthreads();

            #pragma unroll 8
            for (int k = 0; k < kc; ++k) {
                float4 a4 = *(const float4*)(sA + k * 68 + rg * 4);
                ulonglong2 b0 = *(const ulonglong2*)(sB + k * 132 + cg * 8);
                ulonglong2 b1 = *(const ulonglong2*)(sB + k * 132 + cg * 8 + 4);
                ull a0 = pk(a4.x, a4.x), a1 = pk(a4.y, a4.y);
                ull a2 = pk(a4.z, a4.z), a3 = pk(a4.w, a4.w);
                ffma2(acc[0][0], b0.x, a0); ffma2(acc[0][1], b0.y, a0);
                ffma2(acc[0][2], b1.x, a0); ffma2(acc[0][3], b1.y, a0);
                ffma2(acc[1][0], b0.x, a1); ffma2(acc[1][1], b0.y, a1);
                ffma2(acc[1][2], b1.x, a1); ffma2(acc[1][3], b1.y, a1);
                ffma2(acc[2][0], b0.x, a2); ffma2(acc[2][1], b0.y, a2);
                ffma2(acc[2][2], b1.x, a2); ffma2(acc[2][3], b1.y, a2);
                ffma2(acc[3][0], b0.x, a3); ffma2(acc[3][1], b0.y, a3);
                ffma2(acc[3][2], b1.x, a3); ffma2(acc[3][3], b1.y, a3);
            }
        }

        // epilogue: zc[row][half*128 + col] = tanh(acc + bias)
        #pragma unroll
        for (int i = 0; i < 4; ++i) {
            float* zrow = zc + (rg * 4 + i) * ZC_STRIDE + half * 128 + cg * 8;
            #pragma unroll
            for (int p = 0; p < 4; ++p) {
                float v0, v1; upk(acc[i][p], v0, v1);
                zrow[2 * p]     = tanhacc(v0 + sbias[half * 128 + cg * 8 + 2 * p]);
                zrow[2 * p + 1] = tanhacc(v1 + sbias[half * 128 + cg * 8 + 2 * p + 1]);
            }
        }
        __syncthreads();
    }

    // ---- tail ----
    const int row = tid >> 2;        // 0..63
    const int cch = tid & 3;         // 0..3
    const float* __restrict__ W1 = P.p[23];
    const float* __restrict__ W2 = P.p[25];

    // z1 = tanh(W1 @ zc_row + b1), two passes of 40 u
    #pragma unroll 1
    for (int pass = 0; pass < 2; ++pass) {
        __syncthreads();
        for (int idx = tid; idx < 40 * 64; idx += 256) {
            int q = idx & 63, uu = idx >> 6;
            *(float4*)(r1 + uu * SW1_STRIDE + q * 4) =
                *(const float4*)(W1 + (pass * 40 + uu) * 256 + q * 4);
        }
        __syncthreads();
        const ulonglong2* zr = (const ulonglong2*)(zc + row * ZC_STRIDE);
        #pragma unroll 1
        for (int i = 0; i < 10; ++i) {
            int ul = cch * 10 + i;
            const ulonglong2* w1 = (const ulonglong2*)(r1 + ul * SW1_STRIDE);
            ull s0 = 0ULL, s1 = 0ULL, s2 = 0ULL, s3 = 0ULL;
            #pragma unroll
            for (int q = 0; q < 64; q += 2) {
                ulonglong2 wa = w1[q], wb = w1[q + 1];
                ulonglong2 za = zr[q], zb = zr[q + 1];
                ffma2(s0, wa.x, za.x); ffma2(s1, wa.y, za.y);
                ffma2(s2, wb.x, zb.x); ffma2(s3, wb.y, zb.y);
            }
            float a0, a1, a2, a3, a4, a5, a6, a7;
            upk(s0, a0, a1); upk(s1, a2, a3); upk(s2, a4, a5); upk(s3, a6, a7);
            int u = pass * 40 + ul;
            float s = sb1[u] + (a0 + a1) + (a2 + a3) + (a4 + a5) + (a6 + a7);
            z1s[row * Z1_STRIDE + u] = tanhacc(s);
        }
    }

    // z2 = tanh(W2 @ z1 + b2)
    __syncthreads();
    for (int idx = tid; idx < 3200; idx += 256) {
        int v = idx / 80, kk = idx - v * 80;
        r1[v * SW2_STRIDE + kk] = W2[idx];
    }
    __syncthreads();
    {
        const ulonglong2* zr = (const ulonglong2*)(z1s + row * Z1_STRIDE);
        #pragma unroll 1
        for (int i = 0; i < 10; ++i) {
            int v = cch * 10 + i;
            const ulonglong2* w2 = (const ulonglong2*)(r1 + v * SW2_STRIDE);
            ull s0 = 0ULL, s1 = 0ULL;
            #pragma unroll
            for (int q = 0; q < 20; ++q) {
                ulonglong2 w = w2[q], z = zr[q];
                ffma2(s0, w.x, z.x); ffma2(s1, w.y, z.y);
            }
            float a0, a1, a2, a3;
            upk(s0, a0, a1); upk(s1, a2, a3);
            float s = sb2[v] + (a0 + a1) + (a2 + a3);
            z2s[row * Z2_STRIDE + v] = tanhacc(s);
        }
    }

    // out = sigmoid(W3a @ z2 + so0 + so1 + beff)
    __syncthreads();
    if (tid < 64) {
        int gb = m0 + tid;
        const float* __restrict__ bp  = P.p[18];
        const float* __restrict__ W3b = P.p[27] + 40;
        float be = P.p[28][0];
        #pragma unroll 8
        for (int v = 0; v < 40; ++v) be = fmaf(W3b[v], bp[v], be);
        float r3 = be + g_so[gb] + g_so[B_TOTAL + gb];
        const float* z2r = z2s + tid * Z2_STRIDE;
        #pragma unroll
        for (int v = 0; v < 40; ++v) r3 = fmaf(sw3[v], z2r[v], r3);
        P.out[gb] = sigacc(r3);
    }
}

extern "C" void kernel_launch(void* const* d_in, const int* in_sizes, int n_in,
                              void* d_out, int out_size) {
    (void)in_sizes; (void)n_in; (void)out_size;
    Params P;
    for (int i = 0; i < 29; ++i) P.p[i] = (const float*)d_in[i];
    P.out = (float*)d_out;

    const size_t gsh = (size_t)GEMM_SMEM_FL * sizeof(float);   // ~154.6 KB
    cudaFuncSetAttribute(k_gemm, cudaFuncAttributeMaxDynamicSharedMemorySize, (int)gsh);

    k_wt<<<dim3(100, 2), 1024>>>(P.p[19], P.p[21]);
    k_lstm<<<dim3(256, 2), 128>>>(P);
    k_gemm<<<512, 256, gsh>>>(P);
}